// round 1
// baseline (speedup 1.0000x reference)
#include <cuda_runtime.h>
#include <math.h>

#define B_  2
#define C_  64
#define N_  4096
#define EPSV 1e-5f

// ---------------- scratch (no allocation allowed) ----------------
__device__ float g_q [B_ * N_ * C_];   // [b][n][c]
__device__ float g_k [B_ * N_ * C_];   // [b][n][c]
__device__ float g_v [B_ * N_ * C_];   // [b][n][c]
__device__ float g_hh[B_ * N_ * C_];   // attention out, [b][n][c]
__device__ float g_y [B_ * C_ * N_];   // residual+proj, [b][c][n]

// =================================================================
// Kernel A: q/k/v = W @ x + b   (x: [b][c][n], out: [b][n][c])
// grid (64, 2), 256 threads
// =================================================================
__global__ __launch_bounds__(256) void qkv_kernel(
    const float* __restrict__ x,
    const float* __restrict__ Wq, const float* __restrict__ bq,
    const float* __restrict__ Wk, const float* __restrict__ bk,
    const float* __restrict__ Wv, const float* __restrict__ bv)
{
    const int b  = blockIdx.y;
    const int n0 = blockIdx.x * 64;
    const int tid = threadIdx.x;

    __shared__ float xs[64][64];       // [c][n]
    __shared__ float Ws[3][64][65];    // padded weights [m][o][c]

    // load x tile (coalesced float4)
    for (int i = tid; i < 64 * 16; i += 256) {
        int c = i >> 4, n4 = i & 15;
        float4 t = *(const float4*)(x + ((size_t)(b * C_ + c)) * N_ + n0 + n4 * 4);
        xs[c][n4*4+0] = t.x; xs[c][n4*4+1] = t.y; xs[c][n4*4+2] = t.z; xs[c][n4*4+3] = t.w;
    }
    // load weights
    for (int i = tid; i < 64 * 16; i += 256) {
        int o = i >> 4, c4 = i & 15;
        float4 tq = *(const float4*)(Wq + o * 64 + c4 * 4);
        float4 tk = *(const float4*)(Wk + o * 64 + c4 * 4);
        float4 tv = *(const float4*)(Wv + o * 64 + c4 * 4);
        Ws[0][o][c4*4+0]=tq.x; Ws[0][o][c4*4+1]=tq.y; Ws[0][o][c4*4+2]=tq.z; Ws[0][o][c4*4+3]=tq.w;
        Ws[1][o][c4*4+0]=tk.x; Ws[1][o][c4*4+1]=tk.y; Ws[1][o][c4*4+2]=tk.z; Ws[1][o][c4*4+3]=tk.w;
        Ws[2][o][c4*4+0]=tv.x; Ws[2][o][c4*4+1]=tv.y; Ws[2][o][c4*4+2]=tv.z; Ws[2][o][c4*4+3]=tv.w;
    }
    __syncthreads();

    const int nb = tid & 15;   // n = nb + 16*ni
    const int ob = tid >> 4;   // o = ob*4 + oi

    float acc[3][4][4];
    #pragma unroll
    for (int m = 0; m < 3; m++)
        #pragma unroll
        for (int i = 0; i < 4; i++)
            #pragma unroll
            for (int j = 0; j < 4; j++) acc[m][i][j] = 0.f;

    #pragma unroll 4
    for (int c = 0; c < 64; c++) {
        float xv[4];
        #pragma unroll
        for (int ni = 0; ni < 4; ni++) xv[ni] = xs[c][nb + 16 * ni];
        #pragma unroll
        for (int m = 0; m < 3; m++) {
            float wv[4];
            #pragma unroll
            for (int oi = 0; oi < 4; oi++) wv[oi] = Ws[m][ob * 4 + oi][c];
            #pragma unroll
            for (int oi = 0; oi < 4; oi++)
                #pragma unroll
                for (int ni = 0; ni < 4; ni++)
                    acc[m][oi][ni] = fmaf(wv[oi], xv[ni], acc[m][oi][ni]);
        }
    }

    float* outs[3] = { g_q, g_k, g_v };
    const float* biases[3] = { bq, bk, bv };
    #pragma unroll
    for (int m = 0; m < 3; m++) {
        float* dst = outs[m];
        #pragma unroll
        for (int oi = 0; oi < 4; oi++) {
            int o = ob * 4 + oi;
            float bias = biases[m][o];
            #pragma unroll
            for (int ni = 0; ni < 4; ni++) {
                int n = n0 + nb + 16 * ni;
                dst[((size_t)b * N_ + n) * C_ + o] = acc[m][oi][ni] + bias;
            }
        }
    }
}

// =================================================================
// Kernel B: flash attention.  grid (64, 2), 128 threads.
// Each query handled by a lane pair (half = 32 channels each).
// =================================================================
__global__ __launch_bounds__(128) void attn_kernel()
{
    const int b   = blockIdx.y;
    const int q0  = blockIdx.x * 64;
    const int tid = threadIdx.x;
    const int warp = tid >> 5, lane = tid & 31;
    const int qi   = warp * 16 + (lane & 15);
    const int half = lane >> 4;

    __shared__ float Ks[64][64];
    __shared__ float Vs[64][64];

    float qr[32], o[32];
    {
        const float4* qp = (const float4*)(g_q + ((size_t)b * N_ + q0 + qi) * C_ + half * 32);
        #pragma unroll
        for (int i = 0; i < 8; i++) {
            float4 t = qp[i];
            qr[4*i+0] = t.x; qr[4*i+1] = t.y; qr[4*i+2] = t.z; qr[4*i+3] = t.w;
        }
    }
    #pragma unroll
    for (int c = 0; c < 32; c++) o[c] = 0.f;
    float m = -1e30f, lsum = 0.f;

    for (int kt = 0; kt < N_; kt += 64) {
        __syncthreads();
        const float4* kp = (const float4*)(g_k + ((size_t)b * N_ + kt) * C_);
        const float4* vp = (const float4*)(g_v + ((size_t)b * N_ + kt) * C_);
        #pragma unroll
        for (int i = tid; i < 1024; i += 128) {
            ((float4*)Ks)[i] = kp[i];
            ((float4*)Vs)[i] = vp[i];
        }
        __syncthreads();

        #pragma unroll 2
        for (int j = 0; j < 64; j++) {
            const float* Kr = &Ks[j][half * 32];
            float a0 = 0.f, a1 = 0.f, a2 = 0.f, a3 = 0.f;
            #pragma unroll
            for (int c = 0; c < 32; c += 4) {
                a0 = fmaf(qr[c+0], Kr[c+0], a0);
                a1 = fmaf(qr[c+1], Kr[c+1], a1);
                a2 = fmaf(qr[c+2], Kr[c+2], a2);
                a3 = fmaf(qr[c+3], Kr[c+3], a3);
            }
            float s = (a0 + a1) + (a2 + a3);
            s += __shfl_xor_sync(0xffffffffu, s, 16);

            if (s > m) {                       // rare (~ln N times total)
                float sc = __expf(m - s);
                m = s;
                lsum *= sc;
                #pragma unroll
                for (int c = 0; c < 32; c++) o[c] *= sc;
            }
            float p = __expf(s - m);
            lsum += p;
            const float* Vr = &Vs[j][half * 32];
            #pragma unroll
            for (int c = 0; c < 32; c++) o[c] = fmaf(p, Vr[c], o[c]);
        }
    }

    const float inv = 1.f / lsum;
    float4* op = (float4*)(g_hh + ((size_t)b * N_ + q0 + qi) * C_ + half * 32);
    #pragma unroll
    for (int i = 0; i < 8; i++) {
        float4 t;
        t.x = o[4*i+0] * inv; t.y = o[4*i+1] * inv;
        t.z = o[4*i+2] * inv; t.w = o[4*i+3] * inv;
        op[i] = t;
    }
}

// =================================================================
// Kernel C: y = x + Wp @ hh + bp   (out layout [b][c][n])
// grid (32, 2), 256 threads, n-tile of 128
// =================================================================
__global__ __launch_bounds__(256) void proj_kernel(
    const float* __restrict__ x,
    const float* __restrict__ Wp, const float* __restrict__ bp)
{
    const int b  = blockIdx.y;
    const int n0 = blockIdx.x * 128;
    const int tid = threadIdx.x;

    __shared__ float hs[128][65];   // [n][c] padded
    __shared__ float Wps[64][65];

    for (int i = tid; i < 128 * 16; i += 256) {
        int n = i >> 4, c4 = i & 15;
        float4 t = *(const float4*)(g_hh + ((size_t)b * N_ + n0 + n) * C_ + c4 * 4);
        hs[n][c4*4+0] = t.x; hs[n][c4*4+1] = t.y; hs[n][c4*4+2] = t.z; hs[n][c4*4+3] = t.w;
    }
    for (int i = tid; i < 64 * 16; i += 256) {
        int o = i >> 4, c4 = i & 15;
        float4 t = *(const float4*)(Wp + o * 64 + c4 * 4);
        Wps[o][c4*4+0] = t.x; Wps[o][c4*4+1] = t.y; Wps[o][c4*4+2] = t.z; Wps[o][c4*4+3] = t.w;
    }
    __syncthreads();

    const int nb = tid & 15;   // n = nb + 16*j, j<8
    const int ob = tid >> 4;   // o = ob*4 + i

    float acc[4][8];
    #pragma unroll
    for (int i = 0; i < 4; i++)
        #pragma unroll
        for (int j = 0; j < 8; j++) acc[i][j] = 0.f;

    #pragma unroll 4
    for (int c = 0; c < 64; c++) {
        float hv[8];
        #pragma unroll
        for (int j = 0; j < 8; j++) hv[j] = hs[nb + 16 * j][c];
        float wv[4];
        #pragma unroll
        for (int i = 0; i < 4; i++) wv[i] = Wps[ob * 4 + i][c];
        #pragma unroll
        for (int i = 0; i < 4; i++)
            #pragma unroll
            for (int j = 0; j < 8; j++)
                acc[i][j] = fmaf(wv[i], hv[j], acc[i][j]);
    }

    #pragma unroll
    for (int i = 0; i < 4; i++) {
        int o = ob * 4 + i;
        float bias = bp[o];
        #pragma unroll
        for (int j = 0; j < 8; j++) {
            int n = n0 + nb + 16 * j;
            size_t idx = ((size_t)(b * C_ + o)) * N_ + n;
            g_y[idx] = acc[i][j] + bias + x[idx];
        }
    }
}

// =================================================================
// Kernel D: GroupNorm(32) + Swish.  grid (32, 2), 256 threads.
// Group g = channels {2g, 2g+1} -> 8192 contiguous floats of g_y.
// =================================================================
__global__ __launch_bounds__(256) void gnorm_kernel(
    const float* __restrict__ gamma, const float* __restrict__ beta,
    float* __restrict__ out)
{
    const int b = blockIdx.y, g = blockIdx.x;
    const int tid = threadIdx.x;
    const size_t base = ((size_t)(b * C_ + g * 2)) * N_;
    const float* yb = g_y + base;

    float vals[32];
    float s = 0.f, sq = 0.f;
    #pragma unroll
    for (int i = 0; i < 32; i++) {
        float v = yb[tid + 256 * i];
        vals[i] = v;
        s += v;
        sq = fmaf(v, v, sq);
    }
    // block reduction
    #pragma unroll
    for (int off = 16; off; off >>= 1) {
        s  += __shfl_xor_sync(0xffffffffu, s,  off);
        sq += __shfl_xor_sync(0xffffffffu, sq, off);
    }
    __shared__ float red[16];
    if ((tid & 31) == 0) { red[tid >> 5] = s; red[8 + (tid >> 5)] = sq; }
    __syncthreads();
    float S  = red[0] + red[1] + red[2] + red[3] + red[4] + red[5] + red[6] + red[7];
    float SQ = red[8] + red[9] + red[10] + red[11] + red[12] + red[13] + red[14] + red[15];

    const float mean = S * (1.f / 8192.f);
    const float var  = SQ * (1.f / 8192.f) - mean * mean;
    const float rinv = rsqrtf(var + EPSV);

    const float g0 = gamma[g * 2], g1 = gamma[g * 2 + 1];
    const float b0 = beta[g * 2],  b1 = beta[g * 2 + 1];

    float* ob = out + base;
    #pragma unroll
    for (int i = 0; i < 32; i++) {
        int e = tid + 256 * i;
        float gm = (e < N_) ? g0 : g1;
        float bt = (e < N_) ? b0 : b1;
        float yn = (vals[i] - mean) * rinv * gm + bt;
        ob[e] = yn / (1.f + __expf(-yn));
    }
}

// =================================================================
extern "C" void kernel_launch(void* const* d_in, const int* in_sizes, int n_in,
                              void* d_out, int out_size)
{
    const float* x     = (const float*)d_in[0];
    const float* Wq    = (const float*)d_in[1];
    const float* bq    = (const float*)d_in[2];
    const float* Wk    = (const float*)d_in[3];
    const float* bk    = (const float*)d_in[4];
    const float* Wv    = (const float*)d_in[5];
    const float* bv    = (const float*)d_in[6];
    const float* Wp    = (const float*)d_in[7];
    const float* bp    = (const float*)d_in[8];
    const float* gamma = (const float*)d_in[9];
    const float* beta  = (const float*)d_in[10];
    float* out = (float*)d_out;

    qkv_kernel<<<dim3(64, 2), 256>>>(x, Wq, bq, Wk, bk, Wv, bv);
    attn_kernel<<<dim3(64, 2), 128>>>();
    proj_kernel<<<dim3(32, 2), 256>>>(x, Wp, bp);
    gnorm_kernel<<<dim3(32, 2), 256>>>(gamma, beta, out);
}